// round 2
// baseline (speedup 1.0000x reference)
#include <cuda_runtime.h>
#include <math.h>

// ---------------- problem constants ----------------
#define T_TOK 8192      // B*S = 4*2048
#define DM    1024      // d_model
#define DF    4096      // d_ff
#define NE    8         // experts
#define GHID  512       // gating hidden = D/2
#define NSLOT (T_TOK*2) // 16384 (token, expert) slots, top-2
#define LN_EPS 1e-5f

// ---------------- device scratch (no allocs allowed) ----------------
__device__ float g_gh[T_TOK * GHID];                 // 16 MB gating hidden
__device__ float g_hbuf[(size_t)NSLOT * DF];         // 256 MB expert hidden (grouped rows)
__device__ float g_eo[(size_t)NSLOT * DM];           // 64 MB per-slot expert output
__device__ int   g_cnt[NE];
__device__ int   g_off[NE];
__device__ int   g_cur[NE];
__device__ int   g_te[T_TOK * 2];                    // top-2 expert ids per token
__device__ float g_tg[T_TOK * 2];                    // top-2 gates per token
__device__ int   g_slot[T_TOK * 2];                  // token -> grouped slot positions
__device__ int   g_tok[NSLOT];                       // grouped token ids (by expert)
__device__ float g_psum[NE];                         // softmax prob sums (for load loss)
__device__ float g_loss;

// ---------------- small init kernel ----------------
__global__ void k_init_small() {
    int i = threadIdx.x;
    if (i < NE) { g_cnt[i] = 0; g_cur[i] = 0; g_psum[i] = 0.f; }
}

// ---------------- gating GEMM1: gh = relu(x @ gw1 + gb1), [8192x512], K=1024 ----------------
__global__ __launch_bounds__(256) void k_gate1(const float* __restrict__ x,
                                               const float* __restrict__ gw1,
                                               const float* __restrict__ gb1) {
    __shared__ float As[8][128];
    __shared__ float Bs[8][128];
    int tid = threadIdx.x;
    int row0 = blockIdx.x * 128, col0 = blockIdx.y * 128;
    int trow = (tid / 16) * 8, tcol = (tid % 16) * 8;
    int ar = tid >> 1, ak = (tid & 1) * 4;
    int bk = tid >> 5, bn = (tid & 31) * 4;
    const float* Ab = x + (size_t)(row0 + ar) * DM + ak;
    const float* Bb = gw1 + (size_t)bk * GHID + col0 + bn;
    float acc[8][8] = {};
    for (int k0 = 0; k0 < DM; k0 += 8) {
        float4 av = *(const float4*)(Ab + k0);
        As[ak + 0][ar] = av.x; As[ak + 1][ar] = av.y;
        As[ak + 2][ar] = av.z; As[ak + 3][ar] = av.w;
        *(float4*)&Bs[bk][bn] = *(const float4*)(Bb + (size_t)k0 * GHID);
        __syncthreads();
#pragma unroll
        for (int k = 0; k < 8; k++) {
            float ra[8], rb[8];
#pragma unroll
            for (int i = 0; i < 8; i++) ra[i] = As[k][trow + i];
#pragma unroll
            for (int j = 0; j < 8; j++) rb[j] = Bs[k][tcol + j];
#pragma unroll
            for (int i = 0; i < 8; i++)
#pragma unroll
                for (int j = 0; j < 8; j++) acc[i][j] += ra[i] * rb[j];
        }
        __syncthreads();
    }
#pragma unroll
    for (int i = 0; i < 8; i++)
#pragma unroll
        for (int j = 0; j < 8; j++) {
            int r = row0 + trow + i, c = col0 + tcol + j;
            float v = acc[i][j] + gb1[c];
            g_gh[(size_t)r * GHID + c] = fmaxf(v, 0.f);
        }
}

// ---------------- gating GEMM2 + top2 + softmax + prob sums ----------------
// one warp per token, 8 warps/block
__global__ void k_gate2(const float* __restrict__ gw2, const float* __restrict__ gb2) {
    __shared__ float s_ps[NE];
    int tid = threadIdx.x, lane = tid & 31, w = tid >> 5;
    if (tid < NE) s_ps[tid] = 0.f;
    __syncthreads();
    int t = blockIdx.x * 8 + w;
    float acc[NE] = {};
    const float* gr = g_gh + (size_t)t * GHID;
    for (int j = lane; j < GHID; j += 32) {
        float v = gr[j];
#pragma unroll
        for (int e = 0; e < NE; e++) acc[e] += v * gw2[j * NE + e];
    }
#pragma unroll
    for (int e = 0; e < NE; e++)
#pragma unroll
        for (int o = 16; o > 0; o >>= 1) acc[e] += __shfl_xor_sync(0xffffffffu, acc[e], o);
    if (lane == 0) {
        float lg[NE];
        float m = -1e30f;
#pragma unroll
        for (int e = 0; e < NE; e++) { lg[e] = acc[e] + gb2[e]; m = fmaxf(m, lg[e]); }
        // top-2 (ties -> lower index first, matching lax.top_k)
        int i1 = 0, i2 = -1; float v1 = -1e30f, v2 = -1e30f;
#pragma unroll
        for (int e = 0; e < NE; e++) {
            float v = lg[e];
            if (v > v1) { v2 = v1; i2 = i1; v1 = v; i1 = e; }
            else if (v > v2) { v2 = v; i2 = e; }
        }
        float ex = expf(v2 - v1);
        float inv2 = 1.f / (1.f + ex);
        g_te[t * 2 + 0] = i1; g_te[t * 2 + 1] = i2;
        g_tg[t * 2 + 0] = inv2; g_tg[t * 2 + 1] = ex * inv2;
        atomicAdd(&g_cnt[i1], 1);
        atomicAdd(&g_cnt[i2], 1);
        // full softmax probs for load-balancing loss
        float se = 0.f, pe[NE];
#pragma unroll
        for (int e = 0; e < NE; e++) { pe[e] = expf(lg[e] - m); se += pe[e]; }
        float inv = 1.f / se;
#pragma unroll
        for (int e = 0; e < NE; e++) atomicAdd(&s_ps[e], pe[e] * inv);
    }
    __syncthreads();
    if (tid < NE) atomicAdd(&g_psum[tid], s_ps[tid]);
}

// ---------------- offsets + load loss ----------------
__global__ void k_sched() {
    if (threadIdx.x == 0) {
        int o = 0;
        for (int e = 0; e < NE; e++) { g_off[e] = o; g_cur[e] = o; o += g_cnt[e]; }
        const float tt = 1.f / NE;
        float loss = 0.f;
        for (int e = 0; e < NE; e++) {
            float ep = g_psum[e] / (float)T_TOK;
            loss += tt * (logf(tt) - logf(ep + 1e-8f));
        }
        g_loss = loss;
    }
}

// ---------------- scatter tokens into expert groups ----------------
__global__ void k_scatter() {
    int t = blockIdx.x * blockDim.x + threadIdx.x;
    if (t >= T_TOK) return;
#pragma unroll
    for (int kk = 0; kk < 2; kk++) {
        int e = g_te[t * 2 + kk];
        int p = atomicAdd(&g_cur[e], 1);
        g_tok[p] = t;
        g_slot[t * 2 + kk] = p;
    }
}

// ---------------- expert GEMM1: h = gelu(gather(x) @ we1[e] + be1[e]) ----------------
__global__ __launch_bounds__(256) void k_exp1(const float* __restrict__ x,
                                              const float* __restrict__ we1,
                                              const float* __restrict__ be1) {
    int e = blockIdx.z;
    int cnt = g_cnt[e];
    int row0 = blockIdx.x * 128;
    if (row0 >= cnt) return;
    int off = g_off[e];
    __shared__ float As[8][128];
    __shared__ float Bs[8][128];
    int tid = threadIdx.x;
    int col0 = blockIdx.y * 128;
    int trow = (tid / 16) * 8, tcol = (tid % 16) * 8;
    int ar = tid >> 1, ak = (tid & 1) * 4;
    int bk = tid >> 5, bn = (tid & 31) * 4;
    int arow = row0 + ar;
    bool avalid = arow < cnt;
    const float* Ab = avalid ? (x + (size_t)g_tok[off + arow] * DM + ak) : x;
    const float* Bb = we1 + (size_t)e * DM * DF + (size_t)bk * DF + col0 + bn;
    float acc[8][8] = {};
    for (int k0 = 0; k0 < DM; k0 += 8) {
        float4 av = avalid ? *(const float4*)(Ab + k0) : make_float4(0.f, 0.f, 0.f, 0.f);
        As[ak + 0][ar] = av.x; As[ak + 1][ar] = av.y;
        As[ak + 2][ar] = av.z; As[ak + 3][ar] = av.w;
        *(float4*)&Bs[bk][bn] = *(const float4*)(Bb + (size_t)k0 * DF);
        __syncthreads();
#pragma unroll
        for (int k = 0; k < 8; k++) {
            float ra[8], rb[8];
#pragma unroll
            for (int i = 0; i < 8; i++) ra[i] = As[k][trow + i];
#pragma unroll
            for (int j = 0; j < 8; j++) rb[j] = Bs[k][tcol + j];
#pragma unroll
            for (int i = 0; i < 8; i++)
#pragma unroll
                for (int j = 0; j < 8; j++) acc[i][j] += ra[i] * rb[j];
        }
        __syncthreads();
    }
#pragma unroll
    for (int i = 0; i < 8; i++) {
        int r = row0 + trow + i;
        if (r < cnt) {
#pragma unroll
            for (int j = 0; j < 8; j++) {
                int c = col0 + tcol + j;
                float v = acc[i][j] + be1[e * DF + c];
                v = 0.5f * v * (1.f + erff(v * 0.70710678118654752f));  // exact GELU
                g_hbuf[(size_t)(off + r) * DF + c] = v;
            }
        }
    }
}

// ---------------- expert GEMM2: eo = (h @ we2[e] + be2)*escale + ebias (per slot) ----------------
__global__ __launch_bounds__(256) void k_exp2(const float* __restrict__ we2,
                                              const float* __restrict__ be2,
                                              const float* __restrict__ escale,
                                              const float* __restrict__ ebias) {
    int e = blockIdx.z;
    int cnt = g_cnt[e];
    int row0 = blockIdx.x * 128;
    if (row0 >= cnt) return;
    int off = g_off[e];
    __shared__ float As[8][128];
    __shared__ float Bs[8][128];
    int tid = threadIdx.x;
    int col0 = blockIdx.y * 128;
    int trow = (tid / 16) * 8, tcol = (tid % 16) * 8;
    int ar = tid >> 1, ak = (tid & 1) * 4;
    int bk = tid >> 5, bn = (tid & 31) * 4;
    int arow = row0 + ar;
    bool avalid = arow < cnt;
    const float* Ab = g_hbuf + (size_t)(off + (avalid ? arow : 0)) * DF + ak;
    const float* Bb = we2 + (size_t)e * DF * DM + (size_t)bk * DM + col0 + bn;
    float acc[8][8] = {};
    for (int k0 = 0; k0 < DF; k0 += 8) {
        float4 av = avalid ? *(const float4*)(Ab + k0) : make_float4(0.f, 0.f, 0.f, 0.f);
        As[ak + 0][ar] = av.x; As[ak + 1][ar] = av.y;
        As[ak + 2][ar] = av.z; As[ak + 3][ar] = av.w;
        *(float4*)&Bs[bk][bn] = *(const float4*)(Bb + (size_t)k0 * DM);
        __syncthreads();
#pragma unroll
        for (int k = 0; k < 8; k++) {
            float ra[8], rb[8];
#pragma unroll
            for (int i = 0; i < 8; i++) ra[i] = As[k][trow + i];
#pragma unroll
            for (int j = 0; j < 8; j++) rb[j] = Bs[k][tcol + j];
#pragma unroll
            for (int i = 0; i < 8; i++)
#pragma unroll
                for (int j = 0; j < 8; j++) acc[i][j] += ra[i] * rb[j];
        }
        __syncthreads();
    }
#pragma unroll
    for (int i = 0; i < 8; i++) {
        int r = row0 + trow + i;
        if (r < cnt) {
            float* orow = g_eo + (size_t)(off + r) * DM;
#pragma unroll
            for (int j = 0; j < 8; j += 4) {
                int c = col0 + tcol + j;
                float4 v;
                v.x = (acc[i][j + 0] + be2[e * DM + c + 0]) * escale[e * DM + c + 0] + ebias[e * DM + c + 0];
                v.y = (acc[i][j + 1] + be2[e * DM + c + 1]) * escale[e * DM + c + 1] + ebias[e * DM + c + 1];
                v.z = (acc[i][j + 2] + be2[e * DM + c + 2]) * escale[e * DM + c + 2] + ebias[e * DM + c + 2];
                v.w = (acc[i][j + 3] + be2[e * DM + c + 3]) * escale[e * DM + c + 3] + ebias[e * DM + c + 3];
                *(float4*)(orow + c) = v;
            }
        }
    }
}

// ---------------- final: combine top-2 slots + residual + LayerNorm + loss ----------------
__global__ void k_ln(const float* __restrict__ x, const float* __restrict__ gamma,
                     const float* __restrict__ beta, float* __restrict__ out, int out_size) {
    int t = blockIdx.x;
    int tid = threadIdx.x;
    __shared__ float red[8];
    const float* xr = x + (size_t)t * DM;
    const float* e0 = g_eo + (size_t)g_slot[t * 2 + 0] * DM;
    const float* e1 = g_eo + (size_t)g_slot[t * 2 + 1] * DM;
    float w0 = g_tg[t * 2 + 0], w1 = g_tg[t * 2 + 1];
    float v[4];
    float s = 0.f;
#pragma unroll
    for (int i = 0; i < 4; i++) {
        int c = tid + i * 256;
        v[i] = xr[c] + w0 * e0[c] + w1 * e1[c];
        s += v[i];
    }
    // block reduce (256 threads = 8 warps)
#pragma unroll
    for (int o = 16; o > 0; o >>= 1) s += __shfl_xor_sync(0xffffffffu, s, o);
    if ((tid & 31) == 0) red[tid >> 5] = s;
    __syncthreads();
    float tot = 0.f;
#pragma unroll
    for (int i = 0; i < 8; i++) tot += red[i];
    float mu = tot * (1.f / DM);
    float s2 = 0.f;
#pragma unroll
    for (int i = 0; i < 4; i++) { float d = v[i] - mu; s2 += d * d; }
#pragma unroll
    for (int o = 16; o > 0; o >>= 1) s2 += __shfl_xor_sync(0xffffffffu, s2, o);
    __syncthreads();
    if ((tid & 31) == 0) red[tid >> 5] = s2;
    __syncthreads();
    float tot2 = 0.f;
#pragma unroll
    for (int i = 0; i < 8; i++) tot2 += red[i];
    float inv = rsqrtf(tot2 * (1.f / DM) + LN_EPS);
#pragma unroll
    for (int i = 0; i < 4; i++) {
        int c = tid + i * 256;
        out[(size_t)t * DM + c] = (v[i] - mu) * inv * gamma[c] + beta[c];
    }
    if (t == 0 && tid == 0 && out_size > T_TOK * DM) out[T_TOK * DM] = g_loss;
}

// ---------------- launch ----------------
extern "C" void kernel_launch(void* const* d_in, const int* in_sizes, int n_in,
                              void* d_out, int out_size) {
    const float* x      = (const float*)d_in[0];
    const float* gw1    = (const float*)d_in[1];
    const float* gb1    = (const float*)d_in[2];
    const float* gw2    = (const float*)d_in[3];
    const float* gb2    = (const float*)d_in[4];
    const float* we1    = (const float*)d_in[5];
    const float* be1    = (const float*)d_in[6];
    const float* we2    = (const float*)d_in[7];
    const float* be2    = (const float*)d_in[8];
    const float* escale = (const float*)d_in[9];
    const float* ebias  = (const float*)d_in[10];
    const float* gamma  = (const float*)d_in[11];
    const float* beta   = (const float*)d_in[12];
    float* out = (float*)d_out;

    k_init_small<<<1, 32>>>();

    // gating
    k_gate1<<<dim3(T_TOK / 128, GHID / 128), 256>>>(x, gw1, gb1);
    k_gate2<<<T_TOK / 8, 256>>>(gw2, gb2);
    k_sched<<<1, 32>>>();
    k_scatter<<<(T_TOK + 255) / 256, 256>>>();

    // grouped expert FFN (top-2 only)
    k_exp1<<<dim3(NSLOT / 128, DF / 128, NE), 256>>>(x, we1, be1);
    k_exp2<<<dim3(NSLOT / 128, DM / 128, NE), 256>>>(we2, be2, escale, ebias);

    // combine + residual + LayerNorm + loss
    k_ln<<<T_TOK, 256>>>(x, gamma, beta, out, out_size);
}

// round 3
// speedup vs baseline: 2.7462x; 2.7462x over previous
#include <cuda_runtime.h>
#include <cstdint>
#include <math.h>

// ---------------- problem constants ----------------
#define T_TOK 8192      // B*S = 4*2048
#define DM    1024      // d_model
#define DF    4096      // d_ff
#define NE    8         // experts
#define GHID  512       // gating hidden = D/2
#define NSLOT (T_TOK*2) // 16384 (token, expert) slots, top-2
#define LN_EPS 1e-5f

// ---------------- device scratch (no allocs allowed) ----------------
__device__ float g_gh[T_TOK * GHID];                 // 16 MB gating hidden
__device__ float g_hbuf[(size_t)NSLOT * DF];         // 256 MB expert hidden (grouped rows)
__device__ float g_eo[(size_t)NSLOT * DM];           // 64 MB per-slot expert output
__device__ int   g_cnt[NE];
__device__ int   g_off[NE];
__device__ int   g_cur[NE];
__device__ int   g_te[T_TOK * 2];
__device__ float g_tg[T_TOK * 2];
__device__ int   g_slot[T_TOK * 2];
__device__ int   g_tok[NSLOT];
__device__ float g_psum[NE];
__device__ float g_loss;

// ---------------- PTX helpers ----------------
__device__ __forceinline__ uint32_t f2tf32(float f) {
    uint32_t r;
    asm("cvt.rna.tf32.f32 %0, %1;" : "=r"(r) : "f"(f));
    return r;
}
__device__ __forceinline__ void mma_tf32(float* c, const uint32_t* a, const uint32_t* b) {
    asm volatile(
        "mma.sync.aligned.m16n8k8.row.col.f32.tf32.tf32.f32 "
        "{%0,%1,%2,%3},{%4,%5,%6,%7},{%8,%9},{%0,%1,%2,%3};"
        : "+f"(c[0]), "+f"(c[1]), "+f"(c[2]), "+f"(c[3])
        : "r"(a[0]), "r"(a[1]), "r"(a[2]), "r"(a[3]), "r"(b[0]), "r"(b[1]));
}
__device__ __forceinline__ void cp16(void* smem, const void* g) {
    uint32_t s = (uint32_t)__cvta_generic_to_shared(smem);
    asm volatile("cp.async.cg.shared.global [%0],[%1],16;" :: "r"(s), "l"(g));
}
__device__ __forceinline__ void cp_commit() { asm volatile("cp.async.commit_group;"); }
__device__ __forceinline__ void cp_wait1() { asm volatile("cp.async.wait_group 1;"); }
__device__ __forceinline__ void cp_wait0() { asm volatile("cp.async.wait_group 0;"); }

// tile geometry for tf32 GEMM kernels
#define BM 128
#define BN 128
#define BK 16
#define APITCH 20    // BK + 4 -> conflict-free A-fragment reads
#define BPITCH 136   // BN + 8 -> conflict-free B-fragment reads

// ---------------- small init kernel ----------------
__global__ void k_init_small() {
    int i = threadIdx.x;
    if (i < NE) { g_cnt[i] = 0; g_cur[i] = 0; g_psum[i] = 0.f; }
}

// ---------------- gating GEMM1 (full fp32 SIMT for routing accuracy) ----------------
__global__ __launch_bounds__(256) void k_gate1(const float* __restrict__ x,
                                               const float* __restrict__ gw1,
                                               const float* __restrict__ gb1) {
    __shared__ float As[8][128];
    __shared__ float Bs[8][128];
    int tid = threadIdx.x;
    int row0 = blockIdx.x * 128, col0 = blockIdx.y * 128;
    int trow = (tid / 16) * 8, tcol = (tid % 16) * 8;
    int ar = tid >> 1, ak = (tid & 1) * 4;
    int bk = tid >> 5, bn = (tid & 31) * 4;
    const float* Ab = x + (size_t)(row0 + ar) * DM + ak;
    const float* Bb = gw1 + (size_t)bk * GHID + col0 + bn;
    float acc[8][8] = {};
    for (int k0 = 0; k0 < DM; k0 += 8) {
        float4 av = *(const float4*)(Ab + k0);
        As[ak + 0][ar] = av.x; As[ak + 1][ar] = av.y;
        As[ak + 2][ar] = av.z; As[ak + 3][ar] = av.w;
        *(float4*)&Bs[bk][bn] = *(const float4*)(Bb + (size_t)k0 * GHID);
        __syncthreads();
#pragma unroll
        for (int k = 0; k < 8; k++) {
            float ra[8], rb[8];
#pragma unroll
            for (int i = 0; i < 8; i++) ra[i] = As[k][trow + i];
#pragma unroll
            for (int j = 0; j < 8; j++) rb[j] = Bs[k][tcol + j];
#pragma unroll
            for (int i = 0; i < 8; i++)
#pragma unroll
                for (int j = 0; j < 8; j++) acc[i][j] += ra[i] * rb[j];
        }
        __syncthreads();
    }
#pragma unroll
    for (int i = 0; i < 8; i++)
#pragma unroll
        for (int j = 0; j < 8; j++) {
            int r = row0 + trow + i, c = col0 + tcol + j;
            float v = acc[i][j] + gb1[c];
            g_gh[(size_t)r * GHID + c] = fmaxf(v, 0.f);
        }
}

// ---------------- gating GEMM2 + top2 + softmax + prob sums ----------------
__global__ void k_gate2(const float* __restrict__ gw2, const float* __restrict__ gb2) {
    __shared__ float s_ps[NE];
    int tid = threadIdx.x, lane = tid & 31, w = tid >> 5;
    if (tid < NE) s_ps[tid] = 0.f;
    __syncthreads();
    int t = blockIdx.x * 8 + w;
    float acc[NE] = {};
    const float* gr = g_gh + (size_t)t * GHID;
    for (int j = lane; j < GHID; j += 32) {
        float v = gr[j];
#pragma unroll
        for (int e = 0; e < NE; e++) acc[e] += v * gw2[j * NE + e];
    }
#pragma unroll
    for (int e = 0; e < NE; e++)
#pragma unroll
        for (int o = 16; o > 0; o >>= 1) acc[e] += __shfl_xor_sync(0xffffffffu, acc[e], o);
    if (lane == 0) {
        float lg[NE];
        float m = -1e30f;
#pragma unroll
        for (int e = 0; e < NE; e++) { lg[e] = acc[e] + gb2[e]; m = fmaxf(m, lg[e]); }
        int i1 = 0, i2 = -1; float v1 = -1e30f, v2 = -1e30f;
#pragma unroll
        for (int e = 0; e < NE; e++) {
            float v = lg[e];
            if (v > v1) { v2 = v1; i2 = i1; v1 = v; i1 = e; }
            else if (v > v2) { v2 = v; i2 = e; }
        }
        float ex = expf(v2 - v1);
        float inv2 = 1.f / (1.f + ex);
        g_te[t * 2 + 0] = i1; g_te[t * 2 + 1] = i2;
        g_tg[t * 2 + 0] = inv2; g_tg[t * 2 + 1] = ex * inv2;
        atomicAdd(&g_cnt[i1], 1);
        atomicAdd(&g_cnt[i2], 1);
        float se = 0.f, pe[NE];
#pragma unroll
        for (int e = 0; e < NE; e++) { pe[e] = expf(lg[e] - m); se += pe[e]; }
        float inv = 1.f / se;
#pragma unroll
        for (int e = 0; e < NE; e++) atomicAdd(&s_ps[e], pe[e] * inv);
    }
    __syncthreads();
    if (tid < NE) atomicAdd(&g_psum[tid], s_ps[tid]);
}

// ---------------- offsets + load loss ----------------
__global__ void k_sched() {
    if (threadIdx.x == 0) {
        int o = 0;
        for (int e = 0; e < NE; e++) { g_off[e] = o; g_cur[e] = o; o += g_cnt[e]; }
        const float tt = 1.f / NE;
        float loss = 0.f;
        for (int e = 0; e < NE; e++) {
            float ep = g_psum[e] / (float)T_TOK;
            loss += tt * (logf(tt) - logf(ep + 1e-8f));
        }
        g_loss = loss;
    }
}

// ---------------- scatter tokens into expert groups ----------------
__global__ void k_scatter() {
    int t = blockIdx.x * blockDim.x + threadIdx.x;
    if (t >= T_TOK) return;
#pragma unroll
    for (int kk = 0; kk < 2; kk++) {
        int e = g_te[t * 2 + kk];
        int p = atomicAdd(&g_cur[e], 1);
        g_tok[p] = t;
        g_slot[t * 2 + kk] = p;
    }
}

// =======================================================================
// TF32 tensor-core grouped GEMM 1: h = gelu(gather(x) @ we1[e] + be1[e])
// grid: (DF/BN, NSLOT/BM, NE)  (col fastest -> A row-tile L2 reuse)
// =======================================================================
__global__ __launch_bounds__(256) void k_exp1(const float* __restrict__ x,
                                              const float* __restrict__ we1,
                                              const float* __restrict__ be1) {
    int e = blockIdx.z;
    int cnt = g_cnt[e];
    int row0 = blockIdx.y * BM;
    if (row0 >= cnt) return;
    int off = g_off[e];
    int col0 = blockIdx.x * BN;

    __shared__ float As[2][BM * APITCH];
    __shared__ float Bs[2][BK * BPITCH];

    int tid = threadIdx.x;
    int lane = tid & 31, wid = tid >> 5;
    int m0w = (wid >> 2) * 64;      // 2 warps in M
    int n0w = (wid & 3) * 32;       // 4 warps in N

    // A loader: row = tid/2 (fixed), two 16B chunks at c4 = (tid%2)*2 + {0,1}
    int arow = row0 + (tid >> 1);
    int arc = cnt - 1 < arow ? cnt - 1 : arow;     // clamp (finite garbage ok)
    const float* aptr = x + (size_t)g_tok[off + arc] * DM + (tid & 1) * 8;
    float* asmem0 = &As[0][(tid >> 1) * APITCH + (tid & 1) * 8];
    float* asmem1 = &As[1][(tid >> 1) * APITCH + (tid & 1) * 8];
    // B loader: two 16B chunks: f4id = tid, tid+256 -> row = f4id/32, c4 = f4id%32
    const float* bbase = we1 + (size_t)e * DM * DF + col0;
    int br0 = tid >> 5, bc0 = (tid & 31) * 4;

    float acc[4][4][4] = {};

    const int NIT = DM / BK;
    // preload stage 0
    {
        cp16(asmem0, aptr);
        cp16(asmem0 + 4, aptr + 4);
        cp16(&Bs[0][br0 * BPITCH + bc0], bbase + (size_t)br0 * DF + bc0);
        cp16(&Bs[0][(br0 + 8) * BPITCH + bc0], bbase + (size_t)(br0 + 8) * DF + bc0);
        cp_commit();
    }
    for (int it = 0; it < NIT; it++) {
        int cur = it & 1;
        if (it + 1 < NIT) {
            int k0 = (it + 1) * BK;
            float* ad = cur ? asmem0 : asmem1;
            cp16(ad, aptr + k0);
            cp16(ad + 4, aptr + k0 + 4);
            float* bd = &Bs[cur ^ 1][0];
            cp16(&bd[br0 * BPITCH + bc0], bbase + (size_t)(k0 + br0) * DF + bc0);
            cp16(&bd[(br0 + 8) * BPITCH + bc0], bbase + (size_t)(k0 + br0 + 8) * DF + bc0);
            cp_commit();
            cp_wait1();
        } else {
            cp_wait0();
        }
        __syncthreads();
        const float* Ac = As[cur];
        const float* Bc = Bs[cur];
#pragma unroll
        for (int q = 0; q < BK; q += 8) {
            uint32_t af[4][4], bf[4][2];
            int abase = (m0w + (lane >> 2)) * APITCH + (lane & 3) + q;
#pragma unroll
            for (int mi = 0; mi < 4; mi++) {
                int b = abase + mi * 16 * APITCH;
                af[mi][0] = f2tf32(Ac[b]);
                af[mi][1] = f2tf32(Ac[b + 8 * APITCH]);
                af[mi][2] = f2tf32(Ac[b + 4]);
                af[mi][3] = f2tf32(Ac[b + 8 * APITCH + 4]);
            }
            int bbse = ((lane & 3) + q) * BPITCH + n0w + (lane >> 2);
#pragma unroll
            for (int ni = 0; ni < 4; ni++) {
                bf[ni][0] = f2tf32(Bc[bbse + ni * 8]);
                bf[ni][1] = f2tf32(Bc[bbse + 4 * BPITCH + ni * 8]);
            }
#pragma unroll
            for (int mi = 0; mi < 4; mi++)
#pragma unroll
                for (int ni = 0; ni < 4; ni++) mma_tf32(acc[mi][ni], af[mi], bf[ni]);
        }
        __syncthreads();
    }

    // epilogue: bias + exact GELU -> hbuf
#pragma unroll
    for (int mi = 0; mi < 4; mi++) {
        int r0 = row0 + m0w + mi * 16 + (lane >> 2);
#pragma unroll
        for (int half = 0; half < 2; half++) {
            int r = r0 + half * 8;
            if (r < cnt) {
                float* orow = g_hbuf + (size_t)(off + r) * DF;
#pragma unroll
                for (int ni = 0; ni < 4; ni++) {
                    int c = col0 + n0w + ni * 8 + 2 * (lane & 3);
                    float b0 = be1[e * DF + c], b1 = be1[e * DF + c + 1];
                    float v0 = acc[mi][ni][half * 2 + 0] + b0;
                    float v1 = acc[mi][ni][half * 2 + 1] + b1;
                    v0 = 0.5f * v0 * (1.f + erff(v0 * 0.70710678118654752f));
                    v1 = 0.5f * v1 * (1.f + erff(v1 * 0.70710678118654752f));
                    *(float2*)(orow + c) = make_float2(v0, v1);
                }
            }
        }
    }
}

// =======================================================================
// TF32 tensor-core grouped GEMM 2: eo = (h @ we2[e] + be2)*escale + ebias
// grid: (DM/BN, NSLOT/BM, NE)
// =======================================================================
__global__ __launch_bounds__(256) void k_exp2(const float* __restrict__ we2,
                                              const float* __restrict__ be2,
                                              const float* __restrict__ escale,
                                              const float* __restrict__ ebias) {
    int e = blockIdx.z;
    int cnt = g_cnt[e];
    int row0 = blockIdx.y * BM;
    if (row0 >= cnt) return;
    int off = g_off[e];
    int col0 = blockIdx.x * BN;

    __shared__ float As[2][BM * APITCH];
    __shared__ float Bs[2][BK * BPITCH];

    int tid = threadIdx.x;
    int lane = tid & 31, wid = tid >> 5;
    int m0w = (wid >> 2) * 64;
    int n0w = (wid & 3) * 32;

    int arow = row0 + (tid >> 1);
    int arc = cnt - 1 < arow ? cnt - 1 : arow;
    const float* aptr = g_hbuf + (size_t)(off + arc) * DF + (tid & 1) * 8;
    float* asmem0 = &As[0][(tid >> 1) * APITCH + (tid & 1) * 8];
    float* asmem1 = &As[1][(tid >> 1) * APITCH + (tid & 1) * 8];
    const float* bbase = we2 + (size_t)e * DF * DM + col0;
    int br0 = tid >> 5, bc0 = (tid & 31) * 4;

    float acc[4][4][4] = {};

    const int NIT = DF / BK;
    {
        cp16(asmem0, aptr);
        cp16(asmem0 + 4, aptr + 4);
        cp16(&Bs[0][br0 * BPITCH + bc0], bbase + (size_t)br0 * DM + bc0);
        cp16(&Bs[0][(br0 + 8) * BPITCH + bc0], bbase + (size_t)(br0 + 8) * DM + bc0);
        cp_commit();
    }
    for (int it = 0; it < NIT; it++) {
        int cur = it & 1;
        if (it + 1 < NIT) {
            int k0 = (it + 1) * BK;
            float* ad = cur ? asmem0 : asmem1;
            cp16(ad, aptr + k0);
            cp16(ad + 4, aptr + k0 + 4);
            float* bd = &Bs[cur ^ 1][0];
            cp16(&bd[br0 * BPITCH + bc0], bbase + (size_t)(k0 + br0) * DM + bc0);
            cp16(&bd[(br0 + 8) * BPITCH + bc0], bbase + (size_t)(k0 + br0 + 8) * DM + bc0);
            cp_commit();
            cp_wait1();
        } else {
            cp_wait0();
        }
        __syncthreads();
        const float* Ac = As[cur];
        const float* Bc = Bs[cur];
#pragma unroll
        for (int q = 0; q < BK; q += 8) {
            uint32_t af[4][4], bf[4][2];
            int abase = (m0w + (lane >> 2)) * APITCH + (lane & 3) + q;
#pragma unroll
            for (int mi = 0; mi < 4; mi++) {
                int b = abase + mi * 16 * APITCH;
                af[mi][0] = f2tf32(Ac[b]);
                af[mi][1] = f2tf32(Ac[b + 8 * APITCH]);
                af[mi][2] = f2tf32(Ac[b + 4]);
                af[mi][3] = f2tf32(Ac[b + 8 * APITCH + 4]);
            }
            int bbse = ((lane & 3) + q) * BPITCH + n0w + (lane >> 2);
#pragma unroll
            for (int ni = 0; ni < 4; ni++) {
                bf[ni][0] = f2tf32(Bc[bbse + ni * 8]);
                bf[ni][1] = f2tf32(Bc[bbse + 4 * BPITCH + ni * 8]);
            }
#pragma unroll
            for (int mi = 0; mi < 4; mi++)
#pragma unroll
                for (int ni = 0; ni < 4; ni++) mma_tf32(acc[mi][ni], af[mi], bf[ni]);
        }
        __syncthreads();
    }

    // epilogue: (v + be2)*escale + ebias -> per-slot eo
#pragma unroll
    for (int mi = 0; mi < 4; mi++) {
        int r0 = row0 + m0w + mi * 16 + (lane >> 2);
#pragma unroll
        for (int half = 0; half < 2; half++) {
            int r = r0 + half * 8;
            if (r < cnt) {
                float* orow = g_eo + (size_t)(off + r) * DM;
#pragma unroll
                for (int ni = 0; ni < 4; ni++) {
                    int c = col0 + n0w + ni * 8 + 2 * (lane & 3);
                    float2 bb = *(const float2*)(be2 + e * DM + c);
                    float2 ss = *(const float2*)(escale + e * DM + c);
                    float2 eb = *(const float2*)(ebias + e * DM + c);
                    float v0 = (acc[mi][ni][half * 2 + 0] + bb.x) * ss.x + eb.x;
                    float v1 = (acc[mi][ni][half * 2 + 1] + bb.y) * ss.y + eb.y;
                    *(float2*)(orow + c) = make_float2(v0, v1);
                }
            }
        }
    }
}

// ---------------- final: combine top-2 slots + residual + LayerNorm + loss ----------------
__global__ void k_ln(const float* __restrict__ x, const float* __restrict__ gamma,
                     const float* __restrict__ beta, float* __restrict__ out, int out_size) {
    int t = blockIdx.x;
    int tid = threadIdx.x;
    __shared__ float red[8];
    const float* xr = x + (size_t)t * DM;
    const float* e0 = g_eo + (size_t)g_slot[t * 2 + 0] * DM;
    const float* e1 = g_eo + (size_t)g_slot[t * 2 + 1] * DM;
    float w0 = g_tg[t * 2 + 0], w1 = g_tg[t * 2 + 1];
    float v[4];
    float s = 0.f;
#pragma unroll
    for (int i = 0; i < 4; i++) {
        int c = tid + i * 256;
        v[i] = xr[c] + w0 * e0[c] + w1 * e1[c];
        s += v[i];
    }
#pragma unroll
    for (int o = 16; o > 0; o >>= 1) s += __shfl_xor_sync(0xffffffffu, s, o);
    if ((tid & 31) == 0) red[tid >> 5] = s;
    __syncthreads();
    float tot = 0.f;
#pragma unroll
    for (int i = 0; i < 8; i++) tot += red[i];
    float mu = tot * (1.f / DM);
    float s2 = 0.f;
#pragma unroll
    for (int i = 0; i < 4; i++) { float d = v[i] - mu; s2 += d * d; }
#pragma unroll
    for (int o = 16; o > 0; o >>= 1) s2 += __shfl_xor_sync(0xffffffffu, s2, o);
    __syncthreads();
    if ((tid & 31) == 0) red[tid >> 5] = s2;
    __syncthreads();
    float tot2 = 0.f;
#pragma unroll
    for (int i = 0; i < 8; i++) tot2 += red[i];
    float inv = rsqrtf(tot2 * (1.f / DM) + LN_EPS);
#pragma unroll
    for (int i = 0; i < 4; i++) {
        int c = tid + i * 256;
        out[(size_t)t * DM + c] = (v[i] - mu) * inv * gamma[c] + beta[c];
    }
    if (t == 0 && tid == 0 && out_size > T_TOK * DM) out[T_TOK * DM] = g_loss;
}

// ---------------- launch ----------------
extern "C" void kernel_launch(void* const* d_in, const int* in_sizes, int n_in,
                              void* d_out, int out_size) {
    const float* x      = (const float*)d_in[0];
    const float* gw1    = (const float*)d_in[1];
    const float* gb1    = (const float*)d_in[2];
    const float* gw2    = (const float*)d_in[3];
    const float* gb2    = (const float*)d_in[4];
    const float* we1    = (const float*)d_in[5];
    const float* be1    = (const float*)d_in[6];
    const float* we2    = (const float*)d_in[7];
    const float* be2    = (const float*)d_in[8];
    const float* escale = (const float*)d_in[9];
    const float* ebias  = (const float*)d_in[10];
    const float* gamma  = (const float*)d_in[11];
    const float* beta   = (const float*)d_in[12];
    float* out = (float*)d_out;

    k_init_small<<<1, 32>>>();

    // gating (fp32 — routing decisions must stay exact)
    k_gate1<<<dim3(T_TOK / 128, GHID / 128), 256>>>(x, gw1, gb1);
    k_gate2<<<T_TOK / 8, 256>>>(gw2, gb2);
    k_sched<<<1, 32>>>();
    k_scatter<<<(T_TOK + 255) / 256, 256>>>();

    // grouped expert FFN on tf32 tensor cores (top-2 only)
    k_exp1<<<dim3(DF / BN, NSLOT / BM, NE), 256>>>(x, we1, be1);
    k_exp2<<<dim3(DM / BN, NSLOT / BM, NE), 256>>>(we2, be2, escale, ebias);

    // combine + residual + LayerNorm + loss
    k_ln<<<T_TOK, 256>>>(x, gamma, beta, out, out_size);
}

// round 5
// speedup vs baseline: 4.2742x; 1.5564x over previous
#include <cuda_runtime.h>
#include <cuda_fp16.h>
#include <cstdint>
#include <math.h>

// ---------------- problem constants ----------------
#define T_TOK 8192      // B*S
#define DM    1024
#define DF    4096
#define NE    8
#define GHID  512
#define NSLOT (T_TOK*2)
#define LN_EPS 1e-5f

// ---------------- device scratch ----------------
__device__ float  g_gh[T_TOK * GHID];                 // 16 MB gating hidden
__device__ __half g_xh[(size_t)T_TOK * DM];           // 16 MB fp16 x
__device__ __half g_w1h[(size_t)NE * DF * DM];        // 64 MB, [E][n=F][k=D]
__device__ __half g_w2h[(size_t)NE * DM * DF];        // 64 MB, [E][n=D][k=F]
__device__ __half g_hbuf[(size_t)NSLOT * DF];         // 128 MB fp16 hidden (grouped)
__device__ float  g_eo[(size_t)NSLOT * DM];           // 64 MB per-slot expert out
__device__ int    g_cnt[NE];
__device__ int    g_off[NE];
__device__ int    g_cur[NE];
__device__ int    g_te[T_TOK * 2];
__device__ float  g_tg[T_TOK * 2];
__device__ int    g_slot[T_TOK * 2];
__device__ int    g_tok[NSLOT];
__device__ float  g_psum[NE];
__device__ float  g_loss;

// ---------------- PTX helpers ----------------
__device__ __forceinline__ void mma_f16(float* c, const uint32_t* a, const uint32_t* b) {
    asm volatile(
        "mma.sync.aligned.m16n8k16.row.col.f32.f16.f16.f32 "
        "{%0,%1,%2,%3},{%4,%5,%6,%7},{%8,%9},{%0,%1,%2,%3};"
        : "+f"(c[0]), "+f"(c[1]), "+f"(c[2]), "+f"(c[3])
        : "r"(a[0]), "r"(a[1]), "r"(a[2]), "r"(a[3]), "r"(b[0]), "r"(b[1]));
}
__device__ __forceinline__ void cp16(void* smem, const void* g) {
    uint32_t s = (uint32_t)__cvta_generic_to_shared(smem);
    asm volatile("cp.async.cg.shared.global [%0],[%1],16;" :: "r"(s), "l"(g));
}
__device__ __forceinline__ void cp_commit() { asm volatile("cp.async.commit_group;"); }
__device__ __forceinline__ void cp_wait1() { asm volatile("cp.async.wait_group 1;"); }
__device__ __forceinline__ void cp_wait0() { asm volatile("cp.async.wait_group 0;"); }

// smem geometry: rows of 32 data halves padded to 40 (word pitch 20 -> conflict-free)
#define HPITCH 40
#define BKH    32   // K halves per stage

// ---------------- small init ----------------
__global__ void k_init_small() {
    int i = threadIdx.x;
    if (i < NE) { g_cnt[i] = 0; g_cur[i] = 0; g_psum[i] = 0.f; }
}

// ---------------- x -> fp16 ----------------
__global__ void k_cvt_x(const float* __restrict__ x) {
    int i = (blockIdx.x * blockDim.x + threadIdx.x) * 4;
    float4 v = *(const float4*)(x + i);
    __half2* d = (__half2*)(g_xh + i);
    d[0] = __floats2half2_rn(v.x, v.y);
    d[1] = __floats2half2_rn(v.z, v.w);
}

// ---------------- weight transpose+convert: src[e][k][n] -> dst[e][n][k] fp16 ----------------
__global__ void k_trcvt(const float* __restrict__ src, __half* __restrict__ dst,
                        int R /*k*/, int C /*n*/) {
    __shared__ float t[32][33];
    size_t eb = (size_t)blockIdx.z * R * C;
    int c0 = blockIdx.x * 32, r0 = blockIdx.y * 32;
    int tx = threadIdx.x, ty = threadIdx.y;
#pragma unroll
    for (int i = 0; i < 32; i += 8)
        t[ty + i][tx] = src[eb + (size_t)(r0 + ty + i) * C + c0 + tx];
    __syncthreads();
#pragma unroll
    for (int i = 0; i < 32; i += 8)
        dst[eb + (size_t)(c0 + ty + i) * R + r0 + tx] = __float2half_rn(t[tx][ty + i]);
}

// ---------------- gating GEMM1 (fp32 SIMT, routing must stay exact) ----------------
__global__ __launch_bounds__(256) void k_gate1(const float* __restrict__ x,
                                               const float* __restrict__ gw1,
                                               const float* __restrict__ gb1) {
    __shared__ float As[8][128];
    __shared__ float Bs[8][128];
    int tid = threadIdx.x;
    int row0 = blockIdx.x * 128, col0 = blockIdx.y * 128;
    int trow = (tid / 16) * 8, tcol = (tid % 16) * 8;
    int ar = tid >> 1, ak = (tid & 1) * 4;
    int bk = tid >> 5, bn = (tid & 31) * 4;
    const float* Ab = x + (size_t)(row0 + ar) * DM + ak;
    const float* Bb = gw1 + (size_t)bk * GHID + col0 + bn;
    float acc[8][8] = {};
    for (int k0 = 0; k0 < DM; k0 += 8) {
        float4 av = *(const float4*)(Ab + k0);
        As[ak + 0][ar] = av.x; As[ak + 1][ar] = av.y;
        As[ak + 2][ar] = av.z; As[ak + 3][ar] = av.w;
        *(float4*)&Bs[bk][bn] = *(const float4*)(Bb + (size_t)k0 * GHID);
        __syncthreads();
#pragma unroll
        for (int k = 0; k < 8; k++) {
            float ra[8], rb[8];
#pragma unroll
            for (int i = 0; i < 8; i++) ra[i] = As[k][trow + i];
#pragma unroll
            for (int j = 0; j < 8; j++) rb[j] = Bs[k][tcol + j];
#pragma unroll
            for (int i = 0; i < 8; i++)
#pragma unroll
                for (int j = 0; j < 8; j++) acc[i][j] += ra[i] * rb[j];
        }
        __syncthreads();
    }
#pragma unroll
    for (int i = 0; i < 8; i++)
#pragma unroll
        for (int j = 0; j < 8; j++) {
            int r = row0 + trow + i, c = col0 + tcol + j;
            float v = acc[i][j] + gb1[c];
            g_gh[(size_t)r * GHID + c] = fmaxf(v, 0.f);
        }
}

// ---------------- gating GEMM2 + top2 + softmax + prob sums ----------------
__global__ void k_gate2(const float* __restrict__ gw2, const float* __restrict__ gb2) {
    __shared__ float s_ps[NE];
    int tid = threadIdx.x, lane = tid & 31, w = tid >> 5;
    if (tid < NE) s_ps[tid] = 0.f;
    __syncthreads();
    int t = blockIdx.x * 8 + w;
    float acc[NE] = {};
    const float* gr = g_gh + (size_t)t * GHID;
    for (int j = lane; j < GHID; j += 32) {
        float v = gr[j];
#pragma unroll
        for (int e = 0; e < NE; e++) acc[e] += v * gw2[j * NE + e];
    }
#pragma unroll
    for (int e = 0; e < NE; e++)
#pragma unroll
        for (int o = 16; o > 0; o >>= 1) acc[e] += __shfl_xor_sync(0xffffffffu, acc[e], o);
    if (lane == 0) {
        float lg[NE];
        float m = -1e30f;
#pragma unroll
        for (int e = 0; e < NE; e++) { lg[e] = acc[e] + gb2[e]; m = fmaxf(m, lg[e]); }
        int i1 = 0, i2 = -1; float v1 = -1e30f, v2 = -1e30f;
#pragma unroll
        for (int e = 0; e < NE; e++) {
            float v = lg[e];
            if (v > v1) { v2 = v1; i2 = i1; v1 = v; i1 = e; }
            else if (v > v2) { v2 = v; i2 = e; }
        }
        float ex = expf(v2 - v1);
        float inv2 = 1.f / (1.f + ex);
        g_te[t * 2 + 0] = i1; g_te[t * 2 + 1] = i2;
        g_tg[t * 2 + 0] = inv2; g_tg[t * 2 + 1] = ex * inv2;
        atomicAdd(&g_cnt[i1], 1);
        atomicAdd(&g_cnt[i2], 1);
        float se = 0.f, pe[NE];
#pragma unroll
        for (int e = 0; e < NE; e++) { pe[e] = expf(lg[e] - m); se += pe[e]; }
        float inv = 1.f / se;
#pragma unroll
        for (int e = 0; e < NE; e++) atomicAdd(&s_ps[e], pe[e] * inv);
    }
    __syncthreads();
    if (tid < NE) atomicAdd(&g_psum[tid], s_ps[tid]);
}

// ---------------- offsets + load loss ----------------
__global__ void k_sched() {
    if (threadIdx.x == 0) {
        int o = 0;
        for (int e = 0; e < NE; e++) { g_off[e] = o; g_cur[e] = o; o += g_cnt[e]; }
        const float tt = 1.f / NE;
        float loss = 0.f;
        for (int e = 0; e < NE; e++) {
            float ep = g_psum[e] / (float)T_TOK;
            loss += tt * (logf(tt) - logf(ep + 1e-8f));
        }
        g_loss = loss;
    }
}

// ---------------- scatter ----------------
__global__ void k_scatter() {
    int t = blockIdx.x * blockDim.x + threadIdx.x;
    if (t >= T_TOK) return;
#pragma unroll
    for (int kk = 0; kk < 2; kk++) {
        int e = g_te[t * 2 + kk];
        int p = atomicAdd(&g_cur[e], 1);
        g_tok[p] = t;
        g_slot[t * 2 + kk] = p;
    }
}

// =======================================================================
// fp16 mma.sync grouped GEMM, CTA tile 128x128, K-stage 32, 2-stage cp.async.
// MODE 0: hbuf(fp16) = gelu(gather(xh) @ w1h^T + be1)   (K = DM)
// MODE 1: eo(fp32)  = (hbuf @ w2h^T + be2)*escale+ebias (K = DF)
// Warp tile 64x32 (8 warps: 2M x 4N). TN layout, explicit half2 frag loads.
// =======================================================================
template <int MODE>
__global__ __launch_bounds__(256, 2) void k_exp_h(const float* __restrict__ p1,
                                                  const float* __restrict__ p2,
                                                  const float* __restrict__ p3) {
    __shared__ __half As[2][128 * HPITCH];
    __shared__ __half Bs[2][128 * HPITCH];
    int e = blockIdx.z;
    int cnt = g_cnt[e];
    int row0 = blockIdx.y * 128;
    if (row0 >= cnt) return;
    int off = g_off[e];
    int col0 = blockIdx.x * 128;
    int tid = threadIdx.x, lane = tid & 31, wid = tid >> 5;
    int m0w = (wid >> 2) * 64;
    int n0w = (wid & 3) * 32;

    const int KD = MODE ? DF : DM;
    // loader: thread covers row r, chunks cp0, cp0+1 (16B = 8 halves each)
    int r = tid >> 1, cp0 = (tid & 1) * 2;
    int arow = row0 + r;
    int arc = arow < cnt ? arow : cnt - 1;
    const __half* arp = MODE ? (g_hbuf + (size_t)(off + arc) * DF)
                             : (g_xh + (size_t)g_tok[off + arc] * DM);
    const __half* brp = (MODE ? g_w2h : g_w1h) + (size_t)e * DM * DF + (size_t)(col0 + r) * KD;
    __half* adst0 = &As[0][r * HPITCH + cp0 * 8];
    __half* bdst0 = &Bs[0][r * HPITCH + cp0 * 8];
    __half* adst1 = &As[1][r * HPITCH + cp0 * 8];
    __half* bdst1 = &Bs[1][r * HPITCH + cp0 * 8];

    float acc[4][4][4] = {};

    // preload stage 0
    cp16(adst0, arp + cp0 * 8); cp16(adst0 + 8, arp + cp0 * 8 + 8);
    cp16(bdst0, brp + cp0 * 8); cp16(bdst0 + 8, brp + cp0 * 8 + 8);
    cp_commit();

    const int NIT = KD / BKH;
    int gr = lane >> 2, c2 = (lane & 3) * 2;
    for (int it = 0; it < NIT; it++) {
        int cur = it & 1;
        if (it + 1 < NIT) {
            int k0 = (it + 1) * BKH;
            __half* ad = cur ? adst0 : adst1;
            __half* bd = cur ? bdst0 : bdst1;
            cp16(ad, arp + k0 + cp0 * 8); cp16(ad + 8, arp + k0 + cp0 * 8 + 8);
            cp16(bd, brp + k0 + cp0 * 8); cp16(bd + 8, brp + k0 + cp0 * 8 + 8);
            cp_commit();
            cp_wait1();
        } else {
            cp_wait0();
        }
        __syncthreads();
        const __half* Ac = As[cur];
        const __half* Bc = Bs[cur];
#pragma unroll
        for (int q = 0; q < BKH; q += 16) {
            uint32_t af[4][4], bf[4][2];
#pragma unroll
            for (int mi = 0; mi < 4; mi++) {
                const __half* ap = Ac + (m0w + mi * 16 + gr) * HPITCH + q + c2;
                af[mi][0] = *(const uint32_t*)ap;
                af[mi][1] = *(const uint32_t*)(ap + 8 * HPITCH);
                af[mi][2] = *(const uint32_t*)(ap + 8);
                af[mi][3] = *(const uint32_t*)(ap + 8 * HPITCH + 8);
            }
#pragma unroll
            for (int ni = 0; ni < 4; ni++) {
                const __half* bp = Bc + (n0w + ni * 8 + gr) * HPITCH + q + c2;
                bf[ni][0] = *(const uint32_t*)bp;
                bf[ni][1] = *(const uint32_t*)(bp + 8);
            }
#pragma unroll
            for (int mi = 0; mi < 4; mi++)
#pragma unroll
                for (int ni = 0; ni < 4; ni++) mma_f16(acc[mi][ni], af[mi], bf[ni]);
        }
        __syncthreads();
    }

    // epilogue (C frag: rows gr/gr+8, cols 2c..2c+1)
#pragma unroll
    for (int mi = 0; mi < 4; mi++) {
#pragma unroll
        for (int half = 0; half < 2; half++) {
            int rr = row0 + m0w + mi * 16 + gr + half * 8;
            if (rr < cnt) {
                if (MODE == 0) {
                    __half* orow = g_hbuf + (size_t)(off + rr) * DF;
                    const float* bb = p1 + e * DF;
#pragma unroll
                    for (int ni = 0; ni < 4; ni++) {
                        int c = col0 + n0w + ni * 8 + c2;
                        float v0 = acc[mi][ni][half * 2 + 0] + bb[c];
                        float v1 = acc[mi][ni][half * 2 + 1] + bb[c + 1];
                        v0 = 0.5f * v0 * (1.f + erff(v0 * 0.70710678118654752f));
                        v1 = 0.5f * v1 * (1.f + erff(v1 * 0.70710678118654752f));
                        *(__half2*)(orow + c) = __floats2half2_rn(v0, v1);
                    }
                } else {
                    float* orow = g_eo + (size_t)(off + rr) * DM;
                    const float* bb = p1 + e * DM;
                    const float* ss = p2 + e * DM;
                    const float* eb = p3 + e * DM;
#pragma unroll
                    for (int ni = 0; ni < 4; ni++) {
                        int c = col0 + n0w + ni * 8 + c2;
                        float v0 = (acc[mi][ni][half * 2 + 0] + bb[c]) * ss[c] + eb[c];
                        float v1 = (acc[mi][ni][half * 2 + 1] + bb[c + 1]) * ss[c + 1] + eb[c + 1];
                        *(float2*)(orow + c) = make_float2(v0, v1);
                    }
                }
            }
        }
    }
}

// ---------------- final: combine top-2 + residual + LayerNorm + loss ----------------
__global__ void k_ln(const float* __restrict__ x, const float* __restrict__ gamma,
                     const float* __restrict__ beta, float* __restrict__ out, int out_size) {
    int t = blockIdx.x;
    int tid = threadIdx.x;
    __shared__ float red[8];
    const float* xr = x + (size_t)t * DM;
    const float* e0 = g_eo + (size_t)g_slot[t * 2 + 0] * DM;
    const float* e1 = g_eo + (size_t)g_slot[t * 2 + 1] * DM;
    float w0 = g_tg[t * 2 + 0], w1 = g_tg[t * 2 + 1];
    float v[4];
    float s = 0.f;
#pragma unroll
    for (int i = 0; i < 4; i++) {
        int c = tid + i * 256;
        v[i] = xr[c] + w0 * e0[c] + w1 * e1[c];
        s += v[i];
    }
#pragma unroll
    for (int o = 16; o > 0; o >>= 1) s += __shfl_xor_sync(0xffffffffu, s, o);
    if ((tid & 31) == 0) red[tid >> 5] = s;
    __syncthreads();
    float tot = 0.f;
#pragma unroll
    for (int i = 0; i < 8; i++) tot += red[i];
    float mu = tot * (1.f / DM);
    float s2 = 0.f;
#pragma unroll
    for (int i = 0; i < 4; i++) { float d = v[i] - mu; s2 += d * d; }
#pragma unroll
    for (int o = 16; o > 0; o >>= 1) s2 += __shfl_xor_sync(0xffffffffu, s2, o);
    __syncthreads();
    if ((tid & 31) == 0) red[tid >> 5] = s2;
    __syncthreads();
    float tot2 = 0.f;
#pragma unroll
    for (int i = 0; i < 8; i++) tot2 += red[i];
    float inv = rsqrtf(tot2 * (1.f / DM) + LN_EPS);
#pragma unroll
    for (int i = 0; i < 4; i++) {
        int c = tid + i * 256;
        out[(size_t)t * DM + c] = (v[i] - mu) * inv * gamma[c] + beta[c];
    }
    if (t == 0 && tid == 0 && out_size > T_TOK * DM) out[T_TOK * DM] = g_loss;
}

// ---------------- launch ----------------
extern "C" void kernel_launch(void* const* d_in, const int* in_sizes, int n_in,
                              void* d_out, int out_size) {
    const float* x      = (const float*)d_in[0];
    const float* gw1    = (const float*)d_in[1];
    const float* gb1    = (const float*)d_in[2];
    const float* gw2    = (const float*)d_in[3];
    const float* gb2    = (const float*)d_in[4];
    const float* we1    = (const float*)d_in[5];
    const float* be1    = (const float*)d_in[6];
    const float* we2    = (const float*)d_in[7];
    const float* be2    = (const float*)d_in[8];
    const float* escale = (const float*)d_in[9];
    const float* ebias  = (const float*)d_in[10];
    const float* gamma  = (const float*)d_in[11];
    const float* beta   = (const float*)d_in[12];
    float* out = (float*)d_out;

    k_init_small<<<1, 32>>>();

    // fp16 conversions (x and transposed weights)
    k_cvt_x<<<(T_TOK * DM / 4 + 255) / 256, 256>>>(x);
    {
        __half* w1h; cudaGetSymbolAddress((void**)&w1h, g_w1h);
        __half* w2h; cudaGetSymbolAddress((void**)&w2h, g_w2h);
        k_trcvt<<<dim3(DF / 32, DM / 32, NE), dim3(32, 8)>>>(we1, w1h, DM, DF);
        k_trcvt<<<dim3(DM / 32, DF / 32, NE), dim3(32, 8)>>>(we2, w2h, DF, DM);
    }

    // gating (fp32 — routing decisions must stay exact)
    k_gate1<<<dim3(T_TOK / 128, GHID / 128), 256>>>(x, gw1, gb1);
    k_gate2<<<T_TOK / 8, 256>>>(gw2, gb2);
    k_sched<<<1, 32>>>();
    k_scatter<<<(T_TOK + 255) / 256, 256>>>();

    // grouped expert FFN on fp16 mma.sync (top-2 only)
    k_exp_h<0><<<dim3(DF / 128, NSLOT / 128, NE), 256>>>(be1, nullptr, nullptr);
    k_exp_h<1><<<dim3(DM / 128, NSLOT / 128, NE), 256>>>(be2, escale, ebias);

    // combine + residual + LayerNorm + loss
    k_ln<<<T_TOK, 256>>>(x, gamma, beta, out, out_size);
}